// round 1
// baseline (speedup 1.0000x reference)
#include <cuda_runtime.h>
#include <cuda_bf16.h>
#include <cstddef>

#define N_B   2
#define S_LEN 2048
#define HEADS 16
#define HDIM  64
#define EMB   1024
#define SCALE 0.03125f   // 1/sqrt(1024)

// Scratch (alloc-free rule: __device__ globals)
__device__ float g_qp[N_B * S_LEN * EMB];
__device__ float g_kp[N_B * S_LEN * EMB];
__device__ float g_vp[N_B * S_LEN * EMB];
__device__ float g_ao[N_B * S_LEN * EMB];

// ---------------------------------------------------------------------------
// Kernel 1: per-head projection.  X viewed as (65536, 64) row-major (the
// (n,s,h) 64-float chunks are contiguous).  Y[r][e] = sum_d X[r][d] * W[e][d].
// Block: 64 rows x 64 cols, 256 threads, 4x4 micro-tile.
// ---------------------------------------------------------------------------
__global__ __launch_bounds__(256) void proj64(const float* __restrict__ X,
                                              const float* __restrict__ W,
                                              float* __restrict__ Y) {
    __shared__ float Xs[64][68];
    __shared__ float Ws[64][68];
    const int t = threadIdx.x;
    const int rowBase = blockIdx.x * 64;

#pragma unroll
    for (int i = 0; i < 4; i++) {
        int idx = i * 256 + t;          // 0..1023
        int r = idx >> 4;
        int c = (idx & 15) << 2;
        *(float4*)(&Ws[r][c]) = *(const float4*)(W + r * 64 + c);
        *(float4*)(&Xs[r][c]) = *(const float4*)(X + (size_t)(rowBase + r) * 64 + c);
    }
    __syncthreads();

    const int tm = t >> 4, tn = t & 15;
    const int r0 = tm * 4, c0 = tn * 4;
    float acc[4][4] = {};
#pragma unroll 4
    for (int k = 0; k < 64; k += 4) {
        float4 a[4], b[4];
#pragma unroll
        for (int i = 0; i < 4; i++) a[i] = *(float4*)(&Xs[r0 + i][k]);
#pragma unroll
        for (int j = 0; j < 4; j++) b[j] = *(float4*)(&Ws[c0 + j][k]);
#pragma unroll
        for (int i = 0; i < 4; i++)
#pragma unroll
            for (int j = 0; j < 4; j++)
                acc[i][j] += a[i].x * b[j].x + a[i].y * b[j].y +
                             a[i].z * b[j].z + a[i].w * b[j].w;
    }
#pragma unroll
    for (int i = 0; i < 4; i++) {
        float4 o = make_float4(acc[i][0], acc[i][1], acc[i][2], acc[i][3]);
        *(float4*)(Y + (size_t)(rowBase + r0 + i) * 64 + c0) = o;
    }
}

// ---------------------------------------------------------------------------
// Kernel 2: flash attention.  grid = (S/64, N*H).  Block handles 64 queries
// of one (n,h); loops over 32 K-tiles of 64 with online softmax.
// Row stride between consecutive seq positions (same n,h) is EMB floats.
// ---------------------------------------------------------------------------
__global__ __launch_bounds__(256) void flash_attn(const float* __restrict__ Q,
                                                  const float* __restrict__ K,
                                                  const float* __restrict__ V,
                                                  float* __restrict__ O) {
    __shared__ float Qs[64][68];
    __shared__ float Ks[64][68];
    __shared__ float Vs[64][68];
    __shared__ float Ps[64][68];

    const int t  = threadIdx.x;
    const int qt = blockIdx.x;          // query tile 0..31
    const int nh = blockIdx.y;          // 0..31
    const int n  = nh >> 4, h = nh & 15;

    const size_t headOff = ((size_t)n * S_LEN * HEADS + h) * HDIM;
    const float* qb = Q + headOff;
    const float* kb = K + headOff;
    const float* vb = V + headOff;
    const int q0 = qt * 64;

    // Load + pre-scale Q tile
#pragma unroll
    for (int i = 0; i < 4; i++) {
        int idx = i * 256 + t;
        int r = idx >> 4;
        int c = (idx & 15) << 2;
        float4 v = *(const float4*)(qb + (size_t)(q0 + r) * EMB + c);
        v.x *= SCALE; v.y *= SCALE; v.z *= SCALE; v.w *= SCALE;
        *(float4*)(&Qs[r][c]) = v;
    }

    const int tm = t >> 4, tn = t & 15;
    const int r0 = tm * 4, c0 = tn * 4;

    float m[4], l[4], o[4][4];
#pragma unroll
    for (int i = 0; i < 4; i++) {
        m[i] = -1e30f; l[i] = 0.f;
#pragma unroll
        for (int j = 0; j < 4; j++) o[i][j] = 0.f;
    }

    for (int kt = 0; kt < S_LEN / 64; kt++) {
        __syncthreads();   // protect Ks/Vs/Ps reuse (covers Qs load on iter 0)
        const int k0 = kt * 64;
#pragma unroll
        for (int i = 0; i < 4; i++) {
            int idx = i * 256 + t;
            int r = idx >> 4;
            int c = (idx & 15) << 2;
            *(float4*)(&Ks[r][c]) = *(const float4*)(kb + (size_t)(k0 + r) * EMB + c);
            *(float4*)(&Vs[r][c]) = *(const float4*)(vb + (size_t)(k0 + r) * EMB + c);
        }
        __syncthreads();

        // S = Q K^T  (already scaled)
        float acc[4][4] = {};
#pragma unroll 4
        for (int k = 0; k < 64; k += 4) {
            float4 a[4], b[4];
#pragma unroll
            for (int i = 0; i < 4; i++) a[i] = *(float4*)(&Qs[r0 + i][k]);
#pragma unroll
            for (int j = 0; j < 4; j++) b[j] = *(float4*)(&Ks[c0 + j][k]);
#pragma unroll
            for (int i = 0; i < 4; i++)
#pragma unroll
                for (int j = 0; j < 4; j++)
                    acc[i][j] += a[i].x * b[j].x + a[i].y * b[j].y +
                                 a[i].z * b[j].z + a[i].w * b[j].w;
        }

        // Online softmax per row (16 lanes share a row group)
#pragma unroll
        for (int i = 0; i < 4; i++) {
            float mt = fmaxf(fmaxf(acc[i][0], acc[i][1]), fmaxf(acc[i][2], acc[i][3]));
#pragma unroll
            for (int off = 8; off > 0; off >>= 1)
                mt = fmaxf(mt, __shfl_xor_sync(0xffffffffu, mt, off));
            float mn = fmaxf(m[i], mt);
            float al = __expf(m[i] - mn);
            float rs = 0.f;
#pragma unroll
            for (int j = 0; j < 4; j++) {
                float p = __expf(acc[i][j] - mn);
                rs += p;
                Ps[r0 + i][c0 + j] = p;
            }
#pragma unroll
            for (int off = 8; off > 0; off >>= 1)
                rs += __shfl_xor_sync(0xffffffffu, rs, off);
            l[i] = l[i] * al + rs;
            m[i] = mn;
#pragma unroll
            for (int j = 0; j < 4; j++) o[i][j] *= al;
        }
        __syncthreads();

        // O += P V
#pragma unroll 8
        for (int kk = 0; kk < 64; kk++) {
            float4 v4 = *(float4*)(&Vs[kk][c0]);
#pragma unroll
            for (int i = 0; i < 4; i++) {
                float p = Ps[r0 + i][kk];
                o[i][0] += p * v4.x;
                o[i][1] += p * v4.y;
                o[i][2] += p * v4.z;
                o[i][3] += p * v4.w;
            }
        }
    }

    // Normalize + store (attn_out has same (N,S,EMB) flattening as inputs)
#pragma unroll
    for (int i = 0; i < 4; i++) {
        float inv = 1.0f / l[i];
        float4 ov = make_float4(o[i][0] * inv, o[i][1] * inv,
                                o[i][2] * inv, o[i][3] * inv);
        *(float4*)(O + headOff + (size_t)(q0 + r0 + i) * EMB + c0) = ov;
    }
}

// ---------------------------------------------------------------------------
// Kernel 3: Y(4096x1024) = X @ Wo^T + bo.  BM=BN=64, BK=32, 4x4 micro-tile.
// ---------------------------------------------------------------------------
__global__ __launch_bounds__(256) void out_gemm(const float* __restrict__ X,
                                                const float* __restrict__ W,
                                                const float* __restrict__ bias,
                                                float* __restrict__ Y) {
    __shared__ float Xs[64][36];
    __shared__ float Ws[64][36];
    const int t  = threadIdx.x;
    const int m0 = blockIdx.x * 64;
    const int n0 = blockIdx.y * 64;
    const int tm = t >> 4, tn = t & 15;
    const int r0 = tm * 4, c0 = tn * 4;

    float acc[4][4] = {};
    for (int k0 = 0; k0 < EMB; k0 += 32) {
        __syncthreads();
#pragma unroll
        for (int i = 0; i < 2; i++) {
            int idx = i * 256 + t;      // 0..511
            int r = idx >> 3;
            int c = (idx & 7) << 2;
            *(float4*)(&Xs[r][c]) = *(const float4*)(X + (size_t)(m0 + r) * EMB + k0 + c);
            *(float4*)(&Ws[r][c]) = *(const float4*)(W + (size_t)(n0 + r) * EMB + k0 + c);
        }
        __syncthreads();
#pragma unroll
        for (int k = 0; k < 32; k += 4) {
            float4 a[4], b[4];
#pragma unroll
            for (int i = 0; i < 4; i++) a[i] = *(float4*)(&Xs[r0 + i][k]);
#pragma unroll
            for (int j = 0; j < 4; j++) b[j] = *(float4*)(&Ws[c0 + j][k]);
#pragma unroll
            for (int i = 0; i < 4; i++)
#pragma unroll
                for (int j = 0; j < 4; j++)
                    acc[i][j] += a[i].x * b[j].x + a[i].y * b[j].y +
                                 a[i].z * b[j].z + a[i].w * b[j].w;
        }
    }

    const float4 b4 = *(const float4*)(bias + n0 + c0);
#pragma unroll
    for (int i = 0; i < 4; i++) {
        float4 ov = make_float4(acc[i][0] + b4.x, acc[i][1] + b4.y,
                                acc[i][2] + b4.z, acc[i][3] + b4.w);
        *(float4*)(Y + (size_t)(m0 + r0 + i) * EMB + n0 + c0) = ov;
    }
}

// ---------------------------------------------------------------------------
extern "C" void kernel_launch(void* const* d_in, const int* in_sizes, int n_in,
                              void* d_out, int out_size) {
    const float* q  = (const float*)d_in[0];
    const float* k  = (const float*)d_in[1];
    const float* v  = (const float*)d_in[2];
    const float* Wq = (const float*)d_in[3];
    const float* Wk = (const float*)d_in[4];
    const float* Wv = (const float*)d_in[5];
    const float* Wo = (const float*)d_in[6];
    const float* bo = (const float*)d_in[7];
    float* out = (float*)d_out;

    float *qp, *kp, *vp, *ao;
    cudaGetSymbolAddress((void**)&qp, g_qp);
    cudaGetSymbolAddress((void**)&kp, g_kp);
    cudaGetSymbolAddress((void**)&vp, g_vp);
    cudaGetSymbolAddress((void**)&ao, g_ao);

    // 65536 rows / 64 rows-per-block = 1024 blocks per projection
    proj64<<<1024, 256>>>(q, Wq, qp);
    proj64<<<1024, 256>>>(k, Wk, kp);
    proj64<<<1024, 256>>>(v, Wv, vp);

    flash_attn<<<dim3(S_LEN / 64, N_B * HEADS), 256>>>(qp, kp, vp, ao);

    out_gemm<<<dim3((N_B * S_LEN) / 64, EMB / 64), 256>>>(ao, Wo, bo, out);
}

// round 2
// speedup vs baseline: 5.3133x; 5.3133x over previous
#include <cuda_runtime.h>
#include <cuda_bf16.h>
#include <cstdint>
#include <cstddef>

#define N_B   2
#define S_LEN 2048
#define HEADS 16
#define HDIM  64
#define EMB   1024
#define SCALE 0.03125f   // 1/sqrt(1024)
#define FULLM 0xffffffffu

// Scratch (alloc-free rule: __device__ globals)
__device__ float g_qp[N_B * S_LEN * EMB];
__device__ float g_kp[N_B * S_LEN * EMB];
__device__ float g_vp[N_B * S_LEN * EMB];
__device__ float g_ao[N_B * S_LEN * EMB];

// round-to-nearest fp32 -> tf32 (kept as 32-bit pattern)
__device__ __forceinline__ uint32_t f2tf(float x) {
    uint32_t u;
    asm("cvt.rna.tf32.f32 %0, %1;" : "=r"(u) : "f"(x));
    return u;
}
__device__ __forceinline__ float f2tff(float x) { return __uint_as_float(f2tf(x)); }

// D += A(16x8) * B(8x8), tf32 operands, fp32 accum
__device__ __forceinline__ void mma8(float* c, const uint32_t* a, const uint32_t* b) {
    asm volatile(
        "mma.sync.aligned.m16n8k8.row.col.f32.tf32.tf32.f32 "
        "{%0,%1,%2,%3},{%4,%5,%6,%7},{%8,%9},{%0,%1,%2,%3};"
        : "+f"(c[0]), "+f"(c[1]), "+f"(c[2]), "+f"(c[3])
        : "r"(a[0]), "r"(a[1]), "r"(a[2]), "r"(a[3]), "r"(b[0]), "r"(b[1]));
}

// ---------------------------------------------------------------------------
// Projection: Y(65536x64) = X(65536x64) @ W(64x64)^T, per-head weights.
// grid.y selects (q|k|v).  Block = 64 rows, 128 threads = 4 warps x 16 rows.
// ---------------------------------------------------------------------------
__global__ __launch_bounds__(128) void proj_tc(const float* __restrict__ xq,
                                               const float* __restrict__ xk,
                                               const float* __restrict__ xv,
                                               const float* __restrict__ wq,
                                               const float* __restrict__ wk,
                                               const float* __restrict__ wv,
                                               float* __restrict__ yq,
                                               float* __restrict__ yk,
                                               float* __restrict__ yv) {
    __shared__ float Xs[64 * 68];
    __shared__ float Ws[64 * 68];
    const int t = threadIdx.x, lane = t & 31, warp = t >> 5;
    const int tq = lane & 3, gq = lane >> 2;
    const int wm = warp * 16;
    const int rowBase = blockIdx.x * 64;
    const int which = blockIdx.y;
    const float* X = (which == 0) ? xq : (which == 1) ? xk : xv;
    const float* W = (which == 0) ? wq : (which == 1) ? wk : wv;
    float* Y = (which == 0) ? yq : (which == 1) ? yk : yv;

#pragma unroll
    for (int i = 0; i < 8; i++) {
        int idx = i * 128 + t;
        int r = idx >> 4, c = (idx & 15) << 2;
        float4 v = *(const float4*)(X + (size_t)(rowBase + r) * 64 + c);
        *(float4*)(&Xs[r * 68 + c]) =
            make_float4(f2tff(v.x), f2tff(v.y), f2tff(v.z), f2tff(v.w));
        float4 w = *(const float4*)(W + r * 64 + c);
        *(float4*)(&Ws[r * 68 + c]) =
            make_float4(f2tff(w.x), f2tff(w.y), f2tff(w.z), f2tff(w.w));
    }
    __syncthreads();

    const uint32_t* Xu = (const uint32_t*)Xs;
    const uint32_t* Wu = (const uint32_t*)Ws;
    float c[8][4] = {};
#pragma unroll
    for (int k = 0; k < 8; k++) {
        uint32_t a[4];
        int kb = k * 8 + tq;
        a[0] = Xu[(wm + gq) * 68 + kb];
        a[1] = Xu[(wm + gq + 8) * 68 + kb];
        a[2] = Xu[(wm + gq) * 68 + kb + 4];
        a[3] = Xu[(wm + gq + 8) * 68 + kb + 4];
#pragma unroll
        for (int nb = 0; nb < 8; nb++) {
            uint32_t b[2] = { Wu[(nb * 8 + gq) * 68 + kb],
                              Wu[(nb * 8 + gq) * 68 + kb + 4] };
            mma8(c[nb], a, b);
        }
    }
#pragma unroll
    for (int nb = 0; nb < 8; nb++) {
        size_t base = (size_t)(rowBase + wm + gq) * 64 + nb * 8 + 2 * tq;
        *(float2*)(Y + base) = make_float2(c[nb][0], c[nb][1]);
        *(float2*)(Y + base + 8 * 64) = make_float2(c[nb][2], c[nb][3]);
    }
}

// ---------------------------------------------------------------------------
// Flash attention, tensor cores.  grid = (S/64, N*H), 128 thr = 4 warps.
// Q fragments in registers; P passed C-frag -> A-frag via warp shuffles.
// ---------------------------------------------------------------------------
__global__ __launch_bounds__(128) void flash_tc(const float* __restrict__ Q,
                                                const float* __restrict__ K,
                                                const float* __restrict__ V,
                                                float* __restrict__ O) {
    __shared__ float Ks[64 * 68];   // also used to stage Q once
    __shared__ float Vs[64 * 72];
    const int t = threadIdx.x, lane = t & 31, warp = t >> 5;
    const int tq = lane & 3, gq = lane >> 2;
    const int wm = warp * 16;
    const int qt = blockIdx.x, nh = blockIdx.y;
    const int n = nh >> 4, h = nh & 15;
    const size_t headOff = ((size_t)n * S_LEN * HEADS + h) * HDIM;
    const float* qb = Q + headOff;
    const float* kb = K + headOff;
    const float* vb = V + headOff;
    const int q0 = qt * 64;

    // stage Q (scaled, tf32) into Ks, pull A-fragments into registers
#pragma unroll
    for (int i = 0; i < 8; i++) {
        int idx = i * 128 + t;
        int r = idx >> 4, c = (idx & 15) << 2;
        float4 v = *(const float4*)(qb + (size_t)(q0 + r) * EMB + c);
        *(float4*)(&Ks[r * 68 + c]) =
            make_float4(f2tff(v.x * SCALE), f2tff(v.y * SCALE),
                        f2tff(v.z * SCALE), f2tff(v.w * SCALE));
    }
    __syncthreads();
    const uint32_t* Ku = (const uint32_t*)Ks;
    const uint32_t* Vu = (const uint32_t*)Vs;
    uint32_t aQ[8][4];
#pragma unroll
    for (int k = 0; k < 8; k++) {
        int kk = k * 8 + tq;
        aQ[k][0] = Ku[(wm + gq) * 68 + kk];
        aQ[k][1] = Ku[(wm + gq + 8) * 68 + kk];
        aQ[k][2] = Ku[(wm + gq) * 68 + kk + 4];
        aQ[k][3] = Ku[(wm + gq + 8) * 68 + kk + 4];
    }

    float o[8][4] = {};
    float m0 = -1e30f, m1 = -1e30f, l0 = 0.f, l1 = 0.f;

    for (int kt = 0; kt < S_LEN / 64; kt++) {
        __syncthreads();
        const int k0 = kt * 64;
#pragma unroll
        for (int i = 0; i < 8; i++) {
            int idx = i * 128 + t;
            int r = idx >> 4, c = (idx & 15) << 2;
            float4 kv = *(const float4*)(kb + (size_t)(k0 + r) * EMB + c);
            *(float4*)(&Ks[r * 68 + c]) =
                make_float4(f2tff(kv.x), f2tff(kv.y), f2tff(kv.z), f2tff(kv.w));
            float4 vv = *(const float4*)(vb + (size_t)(k0 + r) * EMB + c);
            *(float4*)(&Vs[r * 72 + c]) =
                make_float4(f2tff(vv.x), f2tff(vv.y), f2tff(vv.z), f2tff(vv.w));
        }
        __syncthreads();

        // S = Q K^T  (scaled via Q)
        float c_[8][4] = {};
#pragma unroll
        for (int k = 0; k < 8; k++) {
            int kk = k * 8 + tq;
#pragma unroll
            for (int nb = 0; nb < 8; nb++) {
                uint32_t b[2] = { Ku[(nb * 8 + gq) * 68 + kk],
                                  Ku[(nb * 8 + gq) * 68 + kk + 4] };
                mma8(c_[nb], aQ[k], b);
            }
        }

        // online softmax: rows (wm+gq) -> c0,c1 ; (wm+gq+8) -> c2,c3
        float mt0 = -1e30f, mt1 = -1e30f;
#pragma unroll
        for (int nb = 0; nb < 8; nb++) {
            mt0 = fmaxf(mt0, fmaxf(c_[nb][0], c_[nb][1]));
            mt1 = fmaxf(mt1, fmaxf(c_[nb][2], c_[nb][3]));
        }
#pragma unroll
        for (int off = 1; off <= 2; off <<= 1) {
            mt0 = fmaxf(mt0, __shfl_xor_sync(FULLM, mt0, off));
            mt1 = fmaxf(mt1, __shfl_xor_sync(FULLM, mt1, off));
        }
        float mn0 = fmaxf(m0, mt0), mn1 = fmaxf(m1, mt1);
        float al0 = __expf(m0 - mn0), al1 = __expf(m1 - mn1);
        m0 = mn0; m1 = mn1;
        float rs0 = 0.f, rs1 = 0.f;
#pragma unroll
        for (int nb = 0; nb < 8; nb++) {
            c_[nb][0] = __expf(c_[nb][0] - mn0); rs0 += c_[nb][0];
            c_[nb][1] = __expf(c_[nb][1] - mn0); rs0 += c_[nb][1];
            c_[nb][2] = __expf(c_[nb][2] - mn1); rs1 += c_[nb][2];
            c_[nb][3] = __expf(c_[nb][3] - mn1); rs1 += c_[nb][3];
        }
#pragma unroll
        for (int off = 1; off <= 2; off <<= 1) {
            rs0 += __shfl_xor_sync(FULLM, rs0, off);
            rs1 += __shfl_xor_sync(FULLM, rs1, off);
        }
        l0 = l0 * al0 + rs0;
        l1 = l1 * al1 + rs1;
#pragma unroll
        for (int nb = 0; nb < 8; nb++) {
            o[nb][0] *= al0; o[nb][1] *= al0;
            o[nb][2] *= al1; o[nb][3] *= al1;
            c_[nb][0] = f2tff(c_[nb][0]); c_[nb][1] = f2tff(c_[nb][1]);
            c_[nb][2] = f2tff(c_[nb][2]); c_[nb][3] = f2tff(c_[nb][3]);
        }

        // O += P V : convert C-frag (cols 2q,2q+1) to A-frag (cols q,q+4) via shfl
        const int src = (lane & ~3) + (tq >> 1);
        const bool oddq = (tq & 1);
#pragma unroll
        for (int kg = 0; kg < 8; kg++) {
            uint32_t aP[4];
            float x0 = __shfl_sync(FULLM, c_[kg][0], src);
            float x1 = __shfl_sync(FULLM, c_[kg][1], src);
            aP[0] = __float_as_uint(oddq ? x1 : x0);
            x0 = __shfl_sync(FULLM, c_[kg][2], src);
            x1 = __shfl_sync(FULLM, c_[kg][3], src);
            aP[1] = __float_as_uint(oddq ? x1 : x0);
            x0 = __shfl_sync(FULLM, c_[kg][0], src + 2);
            x1 = __shfl_sync(FULLM, c_[kg][1], src + 2);
            aP[2] = __float_as_uint(oddq ? x1 : x0);
            x0 = __shfl_sync(FULLM, c_[kg][2], src + 2);
            x1 = __shfl_sync(FULLM, c_[kg][3], src + 2);
            aP[3] = __float_as_uint(oddq ? x1 : x0);
#pragma unroll
            for (int nb = 0; nb < 8; nb++) {
                uint32_t b[2] = { Vu[(kg * 8 + tq) * 72 + nb * 8 + gq],
                                  Vu[(kg * 8 + tq + 4) * 72 + nb * 8 + gq] };
                mma8(o[nb], aP, b);
            }
        }
    }

    const float inv0 = 1.0f / l0, inv1 = 1.0f / l1;
#pragma unroll
    for (int nb = 0; nb < 8; nb++) {
        size_t base = headOff + (size_t)(q0 + wm + gq) * EMB + nb * 8 + 2 * tq;
        *(float2*)(O + base) = make_float2(o[nb][0] * inv0, o[nb][1] * inv0);
        *(float2*)(O + base + (size_t)8 * EMB) =
            make_float2(o[nb][2] * inv1, o[nb][3] * inv1);
    }
}

// ---------------------------------------------------------------------------
// Output GEMM: Y(4096x1024) = X @ Wo^T + bo.  Block 64x64, BK=32, 4 warps.
// ---------------------------------------------------------------------------
__global__ __launch_bounds__(128) void out_tc(const float* __restrict__ X,
                                              const float* __restrict__ W,
                                              const float* __restrict__ bias,
                                              float* __restrict__ Y) {
    __shared__ float Xs[64 * 36];
    __shared__ float Ws[64 * 36];
    const int t = threadIdx.x, lane = t & 31, warp = t >> 5;
    const int tq = lane & 3, gq = lane >> 2;
    const int wm = warp * 16;
    const int m0 = blockIdx.x * 64, n0 = blockIdx.y * 64;
    const uint32_t* Xu = (const uint32_t*)Xs;
    const uint32_t* Wu = (const uint32_t*)Ws;

    float c[8][4] = {};
    for (int k0 = 0; k0 < EMB; k0 += 32) {
        __syncthreads();
#pragma unroll
        for (int i = 0; i < 4; i++) {
            int idx = i * 128 + t;
            int r = idx >> 3, cc = (idx & 7) << 2;
            float4 v = *(const float4*)(X + (size_t)(m0 + r) * EMB + k0 + cc);
            *(float4*)(&Xs[r * 36 + cc]) =
                make_float4(f2tff(v.x), f2tff(v.y), f2tff(v.z), f2tff(v.w));
            float4 w = *(const float4*)(W + (size_t)(n0 + r) * EMB + k0 + cc);
            *(float4*)(&Ws[r * 36 + cc]) =
                make_float4(f2tff(w.x), f2tff(w.y), f2tff(w.z), f2tff(w.w));
        }
        __syncthreads();
#pragma unroll
        for (int k = 0; k < 4; k++) {
            int kk = k * 8 + tq;
            uint32_t a[4];
            a[0] = Xu[(wm + gq) * 36 + kk];
            a[1] = Xu[(wm + gq + 8) * 36 + kk];
            a[2] = Xu[(wm + gq) * 36 + kk + 4];
            a[3] = Xu[(wm + gq + 8) * 36 + kk + 4];
#pragma unroll
            for (int nb = 0; nb < 8; nb++) {
                uint32_t b[2] = { Wu[(nb * 8 + gq) * 36 + kk],
                                  Wu[(nb * 8 + gq) * 36 + kk + 4] };
                mma8(c[nb], a, b);
            }
        }
    }

#pragma unroll
    for (int nb = 0; nb < 8; nb++) {
        int col = n0 + nb * 8 + 2 * tq;
        float b0 = __ldg(bias + col), b1 = __ldg(bias + col + 1);
        size_t base = (size_t)(m0 + wm + gq) * EMB + col;
        *(float2*)(Y + base) = make_float2(c[nb][0] + b0, c[nb][1] + b1);
        *(float2*)(Y + base + (size_t)8 * EMB) =
            make_float2(c[nb][2] + b0, c[nb][3] + b1);
    }
}

// ---------------------------------------------------------------------------
extern "C" void kernel_launch(void* const* d_in, const int* in_sizes, int n_in,
                              void* d_out, int out_size) {
    const float* q  = (const float*)d_in[0];
    const float* k  = (const float*)d_in[1];
    const float* v  = (const float*)d_in[2];
    const float* Wq = (const float*)d_in[3];
    const float* Wk = (const float*)d_in[4];
    const float* Wv = (const float*)d_in[5];
    const float* Wo = (const float*)d_in[6];
    const float* bo = (const float*)d_in[7];
    float* out = (float*)d_out;

    float *qp, *kp, *vp, *ao;
    cudaGetSymbolAddress((void**)&qp, g_qp);
    cudaGetSymbolAddress((void**)&kp, g_kp);
    cudaGetSymbolAddress((void**)&vp, g_vp);
    cudaGetSymbolAddress((void**)&ao, g_ao);

    proj_tc<<<dim3(1024, 3), 128>>>(q, k, v, Wq, Wk, Wv, qp, kp, vp);
    flash_tc<<<dim3(S_LEN / 64, N_B * HEADS), 128>>>(qp, kp, vp, ao);
    out_tc<<<dim3((N_B * S_LEN) / 64, EMB / 64), 128>>>(ao, Wo, bo, out);
}